// round 2
// baseline (speedup 1.0000x reference)
#include <cuda_runtime.h>

// Problem constants (fixed shapes from reference)
#define NPTS   1024          // points per instance
#define KINST  8
#define MV     4
#define BTOT   32            // K*M batches
#define RESV   48
#define SPIX   (RESV*RESV)   // 2304
#define TILES  8             // row tiles per batch
#define TROWS  6             // rows per tile
#define TTHREADS (TROWS*RESV) // 288

// Scratch (no allocations allowed)
__device__ float2 g_coords[BTOT * NPTS];   // normalized (x,y) per batch
__device__ float2 g_feats[KINST * NPTS];   // (second_max, max) per point per instance

// ---------------------------------------------------------------------------
// Kernel 1: projection + per-batch min/max normalization + top-2 features
// One block per batch b = k*MV + m, 256 threads, 4 points/thread.
// ---------------------------------------------------------------------------
__global__ void __launch_bounds__(256)
prep_kernel(const float* __restrict__ xyz,
            const float* __restrict__ feats,
            const float* __restrict__ theta,
            const float* __restrict__ phi)
{
    int b = blockIdx.x;
    int k = b >> 2;
    int m = b & 3;

    float th = theta[m], ph = phi[m];
    float st = sinf(th), ct = cosf(th);
    float sp = sinf(ph), cp = cosf(ph);
    // U = (-st, ct, 0); V = (ct*sp, st*sp, cp); center = (ct*cp, st*cp, sp)
    float U0 = -st, U1 = ct;
    float V0 = ct * sp, V1 = st * sp, V2 = cp;
    float cx = ct * cp, cy = st * cp, cz = sp;

    int tid = threadIdx.x;
    float c0v[4], c1v[4];
    float mn0 = 1e30f, mx0 = -1e30f, mn1 = 1e30f, mx1 = -1e30f;

#pragma unroll
    for (int r = 0; r < 4; r++) {
        int p = tid + 256 * r;
        int g = k * NPTS + p;
        float x = xyz[3 * g + 0];
        float y = xyz[3 * g + 1];
        float z = xyz[3 * g + 2];
        float dx = x - cx, dy = y - cy, dz = z - cz;
        float c0 = dx * U0 + dy * U1;
        float c1 = dx * V0 + dy * V1 + dz * V2;
        c0v[r] = c0; c1v[r] = c1;
        mn0 = fminf(mn0, c0); mx0 = fmaxf(mx0, c0);
        mn1 = fminf(mn1, c1); mx1 = fmaxf(mx1, c1);

        if (m == 0) {
            // top-2 of 20 features (ascending-sort last two: [second, max])
            const float* fr = feats + (size_t)g * 20;
            float m1 = -1e30f, m2 = -1e30f;
#pragma unroll
            for (int c = 0; c < 20; c++) {
                float f = fr[c];
                if (f > m1) { m2 = m1; m1 = f; }
                else if (f > m2) { m2 = f; }
            }
            g_feats[g] = make_float2(m2, m1);
        }
    }

    // Block-wide min/max reduction (exact regardless of order)
#pragma unroll
    for (int o = 16; o > 0; o >>= 1) {
        mn0 = fminf(mn0, __shfl_xor_sync(0xffffffffu, mn0, o));
        mx0 = fmaxf(mx0, __shfl_xor_sync(0xffffffffu, mx0, o));
        mn1 = fminf(mn1, __shfl_xor_sync(0xffffffffu, mn1, o));
        mx1 = fmaxf(mx1, __shfl_xor_sync(0xffffffffu, mx1, o));
    }
    __shared__ float smn0[8], smx0[8], smn1[8], smx1[8];
    int lane = tid & 31, wid = tid >> 5;
    if (lane == 0) { smn0[wid] = mn0; smx0[wid] = mx0; smn1[wid] = mn1; smx1[wid] = mx1; }
    __syncthreads();
    mn0 = smn0[0]; mx0 = smx0[0]; mn1 = smn1[0]; mx1 = smx1[0];
#pragma unroll
    for (int w = 1; w < 8; w++) {
        mn0 = fminf(mn0, smn0[w]); mx0 = fmaxf(mx0, smx0[w]);
        mn1 = fminf(mn1, smn1[w]); mx1 = fmaxf(mx1, smx1[w]);
    }

    float ctr0 = (mx0 + mn0) * 0.5f;
    float ctr1 = (mx1 + mn1) * 0.5f;
    float sc0 = fmaxf(mx0 - mn0, 1e-5f) * 0.5f;
    float sc1 = fmaxf(mx1 - mn1, 1e-5f) * 0.5f;

    // ((c-center)/scale + 1) * 0.8 * 48 * 0.5 + 0.1*48 = (t+1)*19.2 + 4.8
#pragma unroll
    for (int r = 0; r < 4; r++) {
        int p = tid + 256 * r;
        float n0 = (__fdiv_rn(c0v[r] - ctr0, sc0) + 1.0f) * 19.2f + 4.8f;
        float n1 = (__fdiv_rn(c1v[r] - ctr1, sc1) + 1.0f) * 19.2f + 4.8f;
        g_coords[b * NPTS + p] = make_float2(n0, n1);
    }
}

// ---------------------------------------------------------------------------
// Kernel 2: per-tile ordered band compaction + ball query + softmax epilogue
// grid (TILES, BTOT), 288 threads = 6 rows x 48 cols; one thread per pixel.
// ---------------------------------------------------------------------------
__global__ void __launch_bounds__(TTHREADS)
mask_kernel(float* __restrict__ out)
{
    int t = blockIdx.x;
    int b = blockIdx.y;
    int k = b >> 2;

    __shared__ float2 sc[NPTS];
    __shared__ float2 sf[NPTS];
    __shared__ int warpcnt[8];

    int tid = threadIdx.x;
    int lane = tid & 31, wid = tid >> 5;

    // A point can satisfy d2<4 for some pixel row in [6t, 6t+5] only if
    // x in (6t-2, 6t+7).  Strict bounds are safe (|dx|>=2 -> d2>=4, not <4).
    float lo = (float)(TROWS * t) - 2.0f;
    float hi = (float)(TROWS * t + TROWS - 1) + 2.0f;

    float2 rc[4], rf[4];
    unsigned bal[4] = {0, 0, 0, 0};
    bool keep[4] = {false, false, false, false};

    if (wid < 8) {  // 8 warps x 128 points, index-ordered
#pragma unroll
        for (int r = 0; r < 4; r++) {
            int p = wid * 128 + r * 32 + lane;
            rc[r] = g_coords[b * NPTS + p];
            rf[r] = g_feats[k * NPTS + p];
        }
        int cnt = 0;
#pragma unroll
        for (int r = 0; r < 4; r++) {
            keep[r] = (rc[r].x > lo) && (rc[r].x < hi);
            bal[r] = __ballot_sync(0xffffffffu, keep[r]);
            cnt += __popc(bal[r]);
        }
        if (lane == 0) warpcnt[wid] = cnt;
    }
    __syncthreads();

    int total = 0, mybase = 0;
#pragma unroll
    for (int w = 0; w < 8; w++) {
        int c = warpcnt[w];
        total += c;
        if (w < wid) mybase += c;
    }

    if (wid < 8) {  // ordered compacted write (index order preserved)
        unsigned lmask = (1u << lane) - 1u;
        int base = mybase;
#pragma unroll
        for (int r = 0; r < 4; r++) {
            int off = __popc(bal[r] & lmask);
            if (keep[r]) { sc[base + off] = rc[r]; sf[base + off] = rf[r]; }
            base += __popc(bal[r]);
        }
    }
    __syncthreads();

    // One pixel per thread
    int i = t * TROWS + tid / RESV;
    int j = tid - (tid / RESV) * RESV;
    float sx = (float)i, sy = (float)j;

    int nsel = 0;
    float f0 = 0.0f, f1 = 0.0f;
#pragma unroll 4
    for (int p = 0; p < total; p++) {
        float2 c = sc[p];                    // broadcast LDS
        float dx = sx - c.x;
        float dy = sy - c.y;
        float d2 = fmaf(dx, dx, dy * dy);
        if (d2 < 4.0f && nsel < 16) {        // first-16 in index order
            float2 f = sf[p];
            f0 += f.x; f1 += f.y; nsel++;
        }
    }

    float occ = fmaxf((float)nsel, 1.0f);
    float a0 = __fdiv_rn(f0, occ);
    float a1 = __fdiv_rn(f1, occ);
    float mx = fmaxf(a0, a1);
    float e0 = expf(a0 - mx);
    float e1 = expf(a1 - mx);
    float s = e0 + e1;
    float nf0 = __fdiv_rn(e0, s);
    float nf1 = __fdiv_rn(e1, s);
    float v = (nf0 == nf1) ? 0.0f : nf1 * 255.0f;

    int base = (b * 3) * SPIX + i * RESV + j;
    out[base] = v;
    out[base + SPIX] = v;
    out[base + 2 * SPIX] = v;
}

// ---------------------------------------------------------------------------
// kernel_launch: inputs are xyz, features, proposals, [res,] theta, phi.
// theta/phi are always the last two inputs; proposals/res are unused because
// the reference assumes contiguous equal instance blocks.
// ---------------------------------------------------------------------------
extern "C" void kernel_launch(void* const* d_in, const int* in_sizes, int n_in,
                              void* d_out, int out_size)
{
    const float* xyz   = (const float*)d_in[0];
    const float* feats = (const float*)d_in[1];
    const float* theta = (const float*)d_in[n_in - 2];
    const float* phi   = (const float*)d_in[n_in - 1];
    float* out = (float*)d_out;

    prep_kernel<<<BTOT, 256>>>(xyz, feats, theta, phi);
    mask_kernel<<<dim3(TILES, BTOT), TTHREADS>>>(out);
}

// round 3
// speedup vs baseline: 1.2679x; 1.2679x over previous
#include <cuda_runtime.h>

#define NPTS  1024
#define BTOT  32
#define RESV  48
#define SPIX  (RESV*RESV)
#define TILES 8
#define TROWS 6
#define NTHR  288           // 9 warps; 6 rows x 48 cols pixels
#define NBINS 8
#define CAP   448           // per-bin capacity (avg occupancy ~55)

// dynamic smem layout (bytes):
//  [0,8192)            float2 scoord[1024]   raw projected coords
//  [8192,16384)        float2 sfeat[1024]    (second_max, max)
//  [16384,73728)       float4 bins[8*448]
//  [73728,73984)       int    wcnt[8][8]
//  [73984,75008)       uint   wbal[8][8][4]
//  [75008,75040)       int    bintot[8]
//  [75040,75184)       float  red[36]        minmax reduction (9 warps x 4)
#define SMEM_BYTES 75184

extern __shared__ char smem_raw[];

__global__ void __launch_bounds__(NTHR)
p2m_kernel(const float* __restrict__ xyz,
           const float* __restrict__ feats,
           const float* __restrict__ theta,
           const float* __restrict__ phi,
           float* __restrict__ out)
{
    float2*   scoord = (float2*)(smem_raw);
    float2*   sfeat  = (float2*)(smem_raw + 8192);
    float4*   bins   = (float4*)(smem_raw + 16384);
    int*      wcnt   = (int*)(smem_raw + 73728);
    unsigned* wbal   = (unsigned*)(smem_raw + 73984);
    int*      bintot = (int*)(smem_raw + 75008);
    float*    red    = (float*)(smem_raw + 75040);

    int t = blockIdx.x;           // row tile
    int b = blockIdx.y;           // batch = k*4 + m
    int k = b >> 2;
    int m = b & 3;
    int tid = threadIdx.x, lane = tid & 31, wid = tid >> 5;

    // ---- view basis ----
    float th = theta[m], ph = phi[m];
    float st = sinf(th), ct = cosf(th);
    float sp = sinf(ph), cp = cosf(ph);
    float U0 = -st, U1 = ct;
    float V0 = ct * sp, V1 = st * sp, V2 = cp;
    float cx = ct * cp, cy = st * cp, cz = sp;

    // ---- Phase A: project + top-2 features + local minmax ----
    float mn0 = 1e30f, mx0 = -1e30f, mn1 = 1e30f, mx1 = -1e30f;
    for (int p = tid; p < NPTS; p += NTHR) {
        int g = k * NPTS + p;
        float x = xyz[3 * g + 0];
        float y = xyz[3 * g + 1];
        float z = xyz[3 * g + 2];
        float dx = x - cx, dy = y - cy, dz = z - cz;
        float c0 = dx * U0 + dy * U1;
        float c1 = dx * V0 + dy * V1 + dz * V2;
        scoord[p] = make_float2(c0, c1);
        mn0 = fminf(mn0, c0); mx0 = fmaxf(mx0, c0);
        mn1 = fminf(mn1, c1); mx1 = fmaxf(mx1, c1);

        // top-2 of 20 features (ascending last two: [second, max])
        const float4* fr = (const float4*)(feats + (size_t)g * 20);
        float t1 = -1e30f, t2 = -1e30f;
#pragma unroll
        for (int q = 0; q < 5; q++) {
            float4 v = fr[q];
            float f;
            f = v.x; if (f > t1) { t2 = t1; t1 = f; } else if (f > t2) t2 = f;
            f = v.y; if (f > t1) { t2 = t1; t1 = f; } else if (f > t2) t2 = f;
            f = v.z; if (f > t1) { t2 = t1; t1 = f; } else if (f > t2) t2 = f;
            f = v.w; if (f > t1) { t2 = t1; t1 = f; } else if (f > t2) t2 = f;
        }
        sfeat[p] = make_float2(t2, t1);
    }

    // ---- Phase B: block minmax reduction (exact: min/max order-invariant) ----
#pragma unroll
    for (int o = 16; o > 0; o >>= 1) {
        mn0 = fminf(mn0, __shfl_xor_sync(0xffffffffu, mn0, o));
        mx0 = fmaxf(mx0, __shfl_xor_sync(0xffffffffu, mx0, o));
        mn1 = fminf(mn1, __shfl_xor_sync(0xffffffffu, mn1, o));
        mx1 = fmaxf(mx1, __shfl_xor_sync(0xffffffffu, mx1, o));
    }
    if (lane == 0) {
        red[wid]      = mn0; red[9 + wid]  = mx0;
        red[18 + wid] = mn1; red[27 + wid] = mx1;
    }
    __syncthreads();
    mn0 = red[0]; mx0 = red[9]; mn1 = red[18]; mx1 = red[27];
#pragma unroll
    for (int w = 1; w < 9; w++) {
        mn0 = fminf(mn0, red[w]);      mx0 = fmaxf(mx0, red[9 + w]);
        mn1 = fminf(mn1, red[18 + w]); mx1 = fmaxf(mx1, red[27 + w]);
    }
    float ctr0 = (mx0 + mn0) * 0.5f;
    float ctr1 = (mx1 + mn1) * 0.5f;
    float sc0  = fmaxf(mx0 - mn0, 1e-5f) * 0.5f;
    float sc1  = fmaxf(mx1 - mn1, 1e-5f) * 0.5f;

    // ---- Phase C1: normalize in regs, per-bin ballots + counts ----
    // strip band: X in (6t-2, 6t+7); bin c band: Y in (6c-2, 6c+7)
    float xlo = (float)(TROWS * t) - 2.0f;
    float xhi = (float)(TROWS * t + TROWS - 1) + 2.0f;

    float2 rc[4]; float2 rf[4]; bool xk[4];
    if (wid < 8) {
#pragma unroll
        for (int r = 0; r < 4; r++) {
            int p = wid * 128 + r * 32 + lane;        // index-ordered mapping
            float2 c = scoord[p];
            float X = (__fdiv_rn(c.x - ctr0, sc0) + 1.0f) * 19.2f + 4.8f;
            float Y = (__fdiv_rn(c.y - ctr1, sc1) + 1.0f) * 19.2f + 4.8f;
            rc[r] = make_float2(X, Y);
            rf[r] = sfeat[p];
            xk[r] = (X > xlo) && (X < xhi);
        }
#pragma unroll
        for (int c = 0; c < NBINS; c++) {
            float ylo = (float)(TROWS * c) - 2.0f;
            float yhi = (float)(TROWS * c + TROWS - 1) + 2.0f;
            int cnt = 0;
#pragma unroll
            for (int r = 0; r < 4; r++) {
                bool kk = xk[r] && (rc[r].y > ylo) && (rc[r].y < yhi);
                unsigned bal = __ballot_sync(0xffffffffu, kk);
                wbal[(wid * NBINS + c) * 4 + r] = bal;
                cnt += __popc(bal);
            }
            wcnt[wid * NBINS + c] = cnt;
        }
    }
    __syncthreads();

    // warp 8 computes per-bin totals while others prepare scatter
    if (wid == 8 && lane < NBINS) {
        int s = 0;
#pragma unroll
        for (int w = 0; w < 8; w++) s += wcnt[w * NBINS + lane];
        bintot[lane] = s;
    }

    // ---- Phase C2: ordered scatter into bins ----
    if (wid < 8) {
        unsigned lmask = (1u << lane) - 1u;
#pragma unroll
        for (int c = 0; c < NBINS; c++) {
            int base = 0;
#pragma unroll
            for (int w = 0; w < 8; w++)
                if (w < wid) base += wcnt[w * NBINS + c];
#pragma unroll
            for (int r = 0; r < 4; r++) {
                unsigned bal = wbal[(wid * NBINS + c) * 4 + r];
                if ((bal >> lane) & 1u) {
                    int idx = base + __popc(bal & lmask);
                    if (idx < CAP)
                        bins[c * CAP + idx] =
                            make_float4(rc[r].x, rc[r].y, rf[r].x, rf[r].y);
                }
                base += __popc(bal);
            }
        }
    }
    __syncthreads();

    // ---- Phase D: per-pixel ball query (first 16 in index order) ----
    int row = tid / RESV;
    int j   = tid - row * RESV;
    int i   = t * TROWS + row;
    int c   = j / TROWS;
    int tot = min(bintot[c], CAP);
    const float4* bp = bins + c * CAP;

    float sx = (float)i, sy = (float)j;
    int nsel = 0;
    float f0 = 0.0f, f1 = 0.0f;
#pragma unroll 4
    for (int p = 0; p < tot; p++) {
        float4 q = bp[p];                     // LDS.128 broadcast
        float ddx = sx - q.x;
        float ddy = sy - q.y;
        float d2 = fmaf(ddx, ddx, ddy * ddy);
        if (d2 < 4.0f && nsel < 16) {
            f0 += q.z; f1 += q.w; nsel++;
        }
    }

    float occ = fmaxf((float)nsel, 1.0f);
    float a0 = __fdiv_rn(f0, occ);
    float a1 = __fdiv_rn(f1, occ);
    float mxv = fmaxf(a0, a1);
    float e0 = expf(a0 - mxv);
    float e1 = expf(a1 - mxv);
    float s  = e0 + e1;
    float nf0 = __fdiv_rn(e0, s);
    float nf1 = __fdiv_rn(e1, s);
    float v = (nf0 == nf1) ? 0.0f : nf1 * 255.0f;

    int base = (b * 3) * SPIX + i * RESV + j;
    out[base]            = v;
    out[base + SPIX]     = v;
    out[base + 2 * SPIX] = v;
}

extern "C" void kernel_launch(void* const* d_in, const int* in_sizes, int n_in,
                              void* d_out, int out_size)
{
    const float* xyz   = (const float*)d_in[0];
    const float* feats = (const float*)d_in[1];
    const float* theta = (const float*)d_in[n_in - 2];
    const float* phi   = (const float*)d_in[n_in - 1];
    float* out = (float*)d_out;

    cudaFuncSetAttribute(p2m_kernel,
                         cudaFuncAttributeMaxDynamicSharedMemorySize,
                         SMEM_BYTES);
    p2m_kernel<<<dim3(TILES, BTOT), NTHR, SMEM_BYTES>>>(xyz, feats, theta, phi, out);
}